// round 11
// baseline (speedup 1.0000x reference)
#include <cuda_runtime.h>
#include <math.h>

#define B 8
#define N 2048
#define C 128
#define F 128
#define GALPHA 0.2f
#define NCH 64
#define CH 32    /* N / NCH */
#define NSG 8    /* super-groups of 8 chunks */

__device__ float g_h[B*N*F];
__device__ float g_e1[B*N], g_e2[B*N];
__device__ float g_P1[B*N], g_N1[B*N];
__device__ int   g_perm[B*N];
__device__ float g_sp2[B*N], g_sn2[B*N];   // sorted exp(e2), exp(0.2*e2)
__device__ float g_ctP[B*NCH*F];           // vector chunk totals
__device__ float g_ctN[B*NCH*F];
__device__ float g_stP[B*NSG*F];           // super-group totals
__device__ float g_stN[B*NSG*F];
__device__ float g_SP[B*(N+1)*F];          // full exclusive prefix of P2*h (sorted)
__device__ float g_SN[B*(N+1)*F];
__device__ float g_sP[B*(N+1)];            // scalar exclusive prefixes
__device__ float g_sN[B*(N+1)];
__device__ int   g_kk[B*N];                // per-row threshold index

// ---------------------------------------------------------------------------
// Kernel 0: e1/e2 via associativity: e = text @ (W @ a). Also P1/N1 tables.
// grid 64 x 256 threads; warp-per-row dot products.
// ---------------------------------------------------------------------------
__global__ __launch_bounds__(256) void k_e(const float* __restrict__ text,
                                           const float* __restrict__ W,
                                           const float* __restrict__ a) {
    __shared__ float wa1[C], wa2[C];
    int t = threadIdx.x;

    if (t < C) {
        float s = 0.f;
        const float* wr = W + (size_t)t * F;
#pragma unroll 8
        for (int f = 0; f < F; ++f) s = fmaf(wr[f], a[f], s);
        wa1[t] = s;
    } else {
        int c = t - C;
        float s = 0.f;
        const float* wr = W + (size_t)c * F;
#pragma unroll 8
        for (int f = 0; f < F; ++f) s = fmaf(wr[f], a[F + f], s);
        wa2[c] = s;
    }
    __syncthreads();

    int warp = t >> 5, lane = t & 31;
    int row0 = blockIdx.x * 256;
    for (int r = warp; r < 256; r += 8) {
        int row = row0 + r;
        const float* tr = text + (size_t)row * C;
        float s1 = 0.f, s2 = 0.f;
#pragma unroll
        for (int i = 0; i < 4; ++i) {
            int c = lane + i * 32;
            float tv = tr[c];
            s1 = fmaf(tv, wa1[c], s1);
            s2 = fmaf(tv, wa2[c], s2);
        }
#pragma unroll
        for (int o = 16; o > 0; o >>= 1) {
            s1 += __shfl_xor_sync(0xffffffffu, s1, o);
            s2 += __shfl_xor_sync(0xffffffffu, s2, o);
        }
        if (lane == 0) {
            g_e1[row] = s1;
            g_e2[row] = s2;
            g_P1[row] = expf(s1);
            g_N1[row] = expf(GALPHA * s1);
        }
    }
}

// ---------------------------------------------------------------------------
// Kernel 1 (merged): blocks 0..255 = GEMM h tile; blocks 256..263 = sort.
// ---------------------------------------------------------------------------
__global__ __launch_bounds__(256) void k_big(const float* __restrict__ text,
                                             const float* __restrict__ W) {
    // --- GEMM smem ---
    __shared__ float a_sh[64][33];
    __shared__ float W_sh[32][128];
    // --- sort smem ---
    __shared__ float key[N];
    __shared__ int   sid[N];
    __shared__ float totP[256], totN[256];

    int t = threadIdx.x;

    if (blockIdx.x < 256) {
        // ============== GEMM: 64x128 tile, 4x8 thread tile ==============
        int row0 = blockIdx.x * 64;
        int tx = t & 15, ty = t >> 4;

        float acc[4][8];
#pragma unroll
        for (int r = 0; r < 4; ++r)
#pragma unroll
            for (int k = 0; k < 8; ++k) acc[r][k] = 0.f;

        for (int k0 = 0; k0 < C; k0 += 32) {
#pragma unroll
            for (int i = 0; i < 2; ++i) {
                int idx = t + i * 256;
                int r = idx >> 3, c4 = idx & 7;
                float4 v = *(const float4*)(text + (size_t)(row0 + r) * C + k0 + c4 * 4);
                a_sh[r][c4 * 4 + 0] = v.x;
                a_sh[r][c4 * 4 + 1] = v.y;
                a_sh[r][c4 * 4 + 2] = v.z;
                a_sh[r][c4 * 4 + 3] = v.w;
            }
#pragma unroll
            for (int i = 0; i < 4; ++i) {
                int idx = t + i * 256;
                int kr = idx >> 5, f4 = idx & 31;
                *(float4*)&W_sh[kr][f4 * 4] =
                    *(const float4*)(W + (size_t)(k0 + kr) * F + f4 * 4);
            }
            __syncthreads();

#pragma unroll
            for (int jj = 0; jj < 32; ++jj) {
                float4 w0 = *(const float4*)&W_sh[jj][tx * 8];
                float4 w1 = *(const float4*)&W_sh[jj][tx * 8 + 4];
#pragma unroll
                for (int r = 0; r < 4; ++r) {
                    float av = a_sh[ty * 4 + r][jj];
                    acc[r][0] = fmaf(av, w0.x, acc[r][0]);
                    acc[r][1] = fmaf(av, w0.y, acc[r][1]);
                    acc[r][2] = fmaf(av, w0.z, acc[r][2]);
                    acc[r][3] = fmaf(av, w0.w, acc[r][3]);
                    acc[r][4] = fmaf(av, w1.x, acc[r][4]);
                    acc[r][5] = fmaf(av, w1.y, acc[r][5]);
                    acc[r][6] = fmaf(av, w1.z, acc[r][6]);
                    acc[r][7] = fmaf(av, w1.w, acc[r][7]);
                }
            }
            __syncthreads();
        }

#pragma unroll
        for (int r = 0; r < 4; ++r) {
            size_t gi = (size_t)(row0 + ty * 4 + r) * F + tx * 8;
            float4 o0 = {acc[r][0], acc[r][1], acc[r][2], acc[r][3]};
            float4 o1 = {acc[r][4], acc[r][5], acc[r][6], acc[r][7]};
            *(float4*)(g_h + gi) = o0;
            *(float4*)(g_h + gi + 4) = o1;
        }
    } else {
        // ============== SORT for batch b (256 threads) ==============
        int b = blockIdx.x - 256;

        for (int j = t; j < N; j += 256) { key[j] = -g_e2[b * N + j]; sid[j] = j; }
        __syncthreads();

        for (int k2 = 2; k2 <= N; k2 <<= 1) {
            for (int j2 = k2 >> 1; j2 > 0; j2 >>= 1) {
                for (int tt = t; tt < N; tt += 256) {
                    int ixj = tt ^ j2;
                    if (ixj > tt) {
                        bool up = ((tt & k2) == 0);
                        float ka = key[tt], kb = key[ixj];
                        if ((ka > kb) == up) {
                            key[tt] = kb; key[ixj] = ka;
                            int tmp = sid[tt]; sid[tt] = sid[ixj]; sid[ixj] = tmp;
                        }
                    }
                }
                __syncthreads();
            }
        }

        // exp tables + per-thread local (8 consecutive) scalar prefix pieces
        float lpi[8], lni[8];   // local inclusive sums
        float accp = 0.f, accn = 0.f;
#pragma unroll
        for (int i = 0; i < 8; ++i) {
            int j = t * 8 + i;
            float kv = key[j];
            float p2 = expf(-kv);
            float n2 = expf(-GALPHA * kv);
            g_perm[b * N + j] = sid[j];
            g_sp2[b * N + j] = p2;
            g_sn2[b * N + j] = n2;
            accp += p2; accn += n2;
            lpi[i] = accp; lni[i] = accn;
        }
        totP[t] = accp;
        totN[t] = accn;
        __syncthreads();

        // H-S inclusive scan over 256 thread-totals
#pragma unroll
        for (int off = 1; off < 256; off <<= 1) {
            float vp = 0.f, vn = 0.f;
            if (t >= off) { vp = totP[t - off]; vn = totN[t - off]; }
            __syncthreads();
            totP[t] += vp; totN[t] += vn;
            __syncthreads();
        }
        float exP = totP[t] - accp;
        float exN = totN[t] - accn;
        size_t o = (size_t)b * (N + 1);
#pragma unroll
        for (int i = 0; i < 8; ++i) {
            int j = t * 8 + i;
            g_sP[o + j] = exP + (i == 0 ? 0.f : lpi[i - 1]);
            g_sN[o + j] = exN + (i == 0 ? 0.f : lni[i - 1]);
        }
        if (t == 255) { g_sP[o + N] = totP[255]; g_sN[o + N] = totN[255]; }

        // threshold index per row
        for (int row = t; row < N; row += 256) {
            float e1 = g_e1[b * N + row];
            int lo = 0, hi = N;
            while (lo < hi) {
                int m = (lo + hi) >> 1;
                if (key[m] < e1) lo = m + 1; else hi = m;
            }
            g_kk[b * N + row] = lo;
        }
    }
}

// ---------------------------------------------------------------------------
// Kernel 3: per-chunk vector totals (perm preloaded -> batched h gathers)
// ---------------------------------------------------------------------------
__global__ __launch_bounds__(128) void k_ctot() {
    int c = blockIdx.x, b = blockIdx.y, f = threadIdx.x;
    int jb = b * N + c * CH;

    int rw[CH];
#pragma unroll
    for (int jj = 0; jj < CH; ++jj) rw[jj] = g_perm[jb + jj];

    float tp = 0.f, tn = 0.f;
#pragma unroll
    for (int jj = 0; jj < CH; ++jj) {
        float hv = g_h[((size_t)(b * N + rw[jj])) * F + f];
        tp = fmaf(g_sp2[jb + jj], hv, tp);
        tn = fmaf(g_sn2[jb + jj], hv, tn);
    }
    size_t ob = ((size_t)(b * NCH + c)) * F + f;
    g_ctP[ob] = tp;
    g_ctN[ob] = tn;
}

// ---------------------------------------------------------------------------
// Kernel 3b: super-group totals (8 chunks each)
// ---------------------------------------------------------------------------
__global__ __launch_bounds__(128) void k_stot() {
    int g = blockIdx.x, b = blockIdx.y, f = threadIdx.x;
    size_t base = ((size_t)(b * NCH + g * 8)) * F + f;
    float sp = 0.f, sn = 0.f;
#pragma unroll
    for (int c = 0; c < 8; ++c) {
        sp += g_ctP[base + (size_t)c * F];
        sn += g_ctN[base + (size_t)c * F];
    }
    size_t ob = ((size_t)(b * NSG + g)) * F + f;
    g_stP[ob] = sp;
    g_stN[ob] = sn;
}

// ---------------------------------------------------------------------------
// Kernel 4: per-chunk offset via 2-level totals + write full prefixes
// ---------------------------------------------------------------------------
__global__ __launch_bounds__(128) void k_scanlocal() {
    int c = blockIdx.x, b = blockIdx.y, f = threadIdx.x;
    int g = c >> 3, r = c & 7;

    float offP = 0.f, offN = 0.f;
    size_t stb = ((size_t)b * NSG) * F + f;
#pragma unroll
    for (int gg = 0; gg < NSG - 1; ++gg) {
        float vp = g_stP[stb + (size_t)gg * F];
        float vn = g_stN[stb + (size_t)gg * F];
        if (gg < g) { offP += vp; offN += vn; }
    }
    size_t ctb = ((size_t)(b * NCH + g * 8)) * F + f;
#pragma unroll
    for (int cc = 0; cc < 7; ++cc) {
        float vp = g_ctP[ctb + (size_t)cc * F];
        float vn = g_ctN[ctb + (size_t)cc * F];
        if (cc < r) { offP += vp; offN += vn; }
    }

    int jb = b * N + c * CH;
    int rw[CH];
#pragma unroll
    for (int jj = 0; jj < CH; ++jj) rw[jj] = g_perm[jb + jj];

    float accP = offP, accN = offN;
    size_t sb = ((size_t)(b * (N + 1) + c * CH)) * F + f;
#pragma unroll
    for (int jj = 0; jj < CH; ++jj) {
        float hv = g_h[((size_t)(b * N + rw[jj])) * F + f];
        g_SP[sb + (size_t)jj * F] = accP;
        g_SN[sb + (size_t)jj * F] = accN;
        accP = fmaf(g_sp2[jb + jj], hv, accP);
        accN = fmaf(g_sn2[jb + jj], hv, accN);
    }
    if (c == NCH - 1) {
        g_SP[((size_t)(b * (N + 1) + N)) * F + f] = accP;
        g_SN[((size_t)(b * (N + 1) + N)) * F + f] = accN;
    }
}

// ---------------------------------------------------------------------------
// Kernel 5: per-row O(1) lookup + elu epilogue
// ---------------------------------------------------------------------------
__global__ __launch_bounds__(128) void k_out(float* __restrict__ out) {
    __shared__ int   kk[32];
    __shared__ float p1s[32], n1s[32], sps[32], sns[32];

    int t = threadIdx.x;
    int b = blockIdx.y;
    int i0 = blockIdx.x * 32;

    if (t < 32) {
        int i = b * N + i0 + t;
        int k = g_kk[i];
        kk[t] = k;
        p1s[t] = g_P1[i];
        n1s[t] = g_N1[i];
        sps[t] = g_sP[(size_t)b * (N + 1) + k];
        sns[t] = g_sN[(size_t)b * (N + 1) + k];
    }
    __syncthreads();

    float totNf = g_SN[((size_t)(b * (N + 1) + N)) * F + t];
    float totNs = g_sN[(size_t)b * (N + 1) + N];

#pragma unroll 4
    for (int r = 0; r < 32; ++r) {
        int k = kk[r];
        size_t sb = ((size_t)(b * (N + 1) + k)) * F + t;
        float SPf = g_SP[sb];
        float SNf = g_SN[sb];

        float P1 = p1s[r], N1v = n1s[r];
        float den = fmaf(P1, sps[r], N1v * (totNs - sns[r]));
        float num = fmaf(P1, SPf, N1v * (totNf - SNf));
        float hv_i = g_h[((size_t)(b * N + i0 + r)) * F + t];
        float x = num / den + GALPHA * hv_i;
        out[((size_t)(b * N + i0 + r)) * F + t] = (x > 0.f) ? x : expm1f(x);
    }
}

extern "C" void kernel_launch(void* const* d_in, const int* in_sizes, int n_in,
                              void* d_out, int out_size) {
    const float* text = (const float*)d_in[0];
    // d_in[1] = adj : unused by the reference computation
    const float* W = (const float*)d_in[2];
    const float* a = (const float*)d_in[3];
    float* out = (float*)d_out;

    k_e<<<(B * N) / 256, 256>>>(text, W, a);
    k_big<<<256 + B, 256>>>(text, W);
    dim3 gc(NCH, B);
    k_ctot<<<gc, 128>>>();
    dim3 gs(NSG, B);
    k_stot<<<gs, 128>>>();
    k_scanlocal<<<gc, 128>>>();
    dim3 go(N / 32, B);
    k_out<<<go, 128>>>(out);
}

// round 12
// speedup vs baseline: 1.2786x; 1.2786x over previous
#include <cuda_runtime.h>
#include <math.h>

#define B 8
#define N 2048
#define C 128
#define F 128
#define GALPHA 0.2f
#define NCH 64
#define CH 32    /* N / NCH */
#define NSG 8    /* super-groups of 8 chunks */

__device__ float g_h[B*N*F];
__device__ float g_e1[B*N], g_e2[B*N];
__device__ float g_P1[B*N], g_N1[B*N];
__device__ int   g_perm[B*N];
__device__ float g_sp2[B*N], g_sn2[B*N];   // sorted exp(e2), exp(0.2*e2)
__device__ float g_ctP[B*NCH*F];           // vector chunk totals
__device__ float g_ctN[B*NCH*F];
__device__ float g_stP[B*NSG*F];           // super-group totals
__device__ float g_stN[B*NSG*F];
__device__ float g_SP[B*(N+1)*F];          // full exclusive prefix of P2*h (sorted)
__device__ float g_SN[B*(N+1)*F];
__device__ float g_sP[B*(N+1)];            // scalar exclusive prefixes
__device__ float g_sN[B*(N+1)];
__device__ int   g_kk[B*N];                // per-row threshold index

// ---------------------------------------------------------------------------
// Kernel 0: e1/e2 via associativity: e = text @ (W @ a); P1/N1 tables.
// ---------------------------------------------------------------------------
__global__ __launch_bounds__(256) void k_e(const float* __restrict__ text,
                                           const float* __restrict__ W,
                                           const float* __restrict__ a) {
    __shared__ float wa1[C], wa2[C];
    int t = threadIdx.x;

    if (t < C) {
        float s = 0.f;
        const float* wr = W + (size_t)t * F;
#pragma unroll 8
        for (int f = 0; f < F; ++f) s = fmaf(wr[f], a[f], s);
        wa1[t] = s;
    } else {
        int c = t - C;
        float s = 0.f;
        const float* wr = W + (size_t)c * F;
#pragma unroll 8
        for (int f = 0; f < F; ++f) s = fmaf(wr[f], a[F + f], s);
        wa2[c] = s;
    }
    __syncthreads();

    int warp = t >> 5, lane = t & 31;
    int row0 = blockIdx.x * 256;
    for (int r = warp; r < 256; r += 8) {
        int row = row0 + r;
        const float* tr = text + (size_t)row * C;
        float s1 = 0.f, s2 = 0.f;
#pragma unroll
        for (int i = 0; i < 4; ++i) {
            int c = lane + i * 32;
            float tv = tr[c];
            s1 = fmaf(tv, wa1[c], s1);
            s2 = fmaf(tv, wa2[c], s2);
        }
#pragma unroll
        for (int o = 16; o > 0; o >>= 1) {
            s1 += __shfl_xor_sync(0xffffffffu, s1, o);
            s2 += __shfl_xor_sync(0xffffffffu, s2, o);
        }
        if (lane == 0) {
            g_e1[row] = s1;
            g_e2[row] = s2;
            g_P1[row] = expf(s1);
            g_N1[row] = expf(GALPHA * s1);
        }
    }
}

// ---------------------------------------------------------------------------
// Kernel 1: 512-thread blocks. Blocks 0..127: two 64-row GEMM sub-tiles
// (proven R6 tile per 256-thread group). Blocks 128..135: per-batch sort.
// ---------------------------------------------------------------------------
struct GemmSmem { float a_sh[2][64][33]; float W_sh[32][128]; };
struct SortSmem { float key[N]; int sid[N]; float totP[512]; float totN[512]; };

__global__ __launch_bounds__(512) void k_gemsort(const float* __restrict__ text,
                                                 const float* __restrict__ W) {
    __shared__ union { GemmSmem g; SortSmem s; } u;
    int t = threadIdx.x;

    if (blockIdx.x < 128) {
        // ===================== GEMM =====================
        int g2 = t >> 8;          // sub-tile 0/1
        int lt = t & 255;
        int row0 = blockIdx.x * 128 + g2 * 64;
        int tx = lt & 15, ty = lt >> 4;

        float acc[4][8];
#pragma unroll
        for (int r = 0; r < 4; ++r)
#pragma unroll
            for (int k = 0; k < 8; ++k) acc[r][k] = 0.f;

        for (int k0 = 0; k0 < C; k0 += 32) {
            // per-sub-tile A panel (64x32)
#pragma unroll
            for (int i = 0; i < 2; ++i) {
                int idx = lt + i * 256;
                int r = idx >> 3, c4 = idx & 7;
                float4 v = *(const float4*)(text + (size_t)(row0 + r) * C + k0 + c4 * 4);
                u.g.a_sh[g2][r][c4 * 4 + 0] = v.x;
                u.g.a_sh[g2][r][c4 * 4 + 1] = v.y;
                u.g.a_sh[g2][r][c4 * 4 + 2] = v.z;
                u.g.a_sh[g2][r][c4 * 4 + 3] = v.w;
            }
            // shared W panel (32x128) loaded by all 512 threads
#pragma unroll
            for (int i = 0; i < 2; ++i) {
                int idx = t + i * 512;
                int kr = idx >> 5, f4 = idx & 31;
                *(float4*)&u.g.W_sh[kr][f4 * 4] =
                    *(const float4*)(W + (size_t)(k0 + kr) * F + f4 * 4);
            }
            __syncthreads();

#pragma unroll
            for (int jj = 0; jj < 32; ++jj) {
                float4 w0 = *(const float4*)&u.g.W_sh[jj][tx * 8];
                float4 w1 = *(const float4*)&u.g.W_sh[jj][tx * 8 + 4];
#pragma unroll
                for (int r = 0; r < 4; ++r) {
                    float av = u.g.a_sh[g2][ty * 4 + r][jj];
                    acc[r][0] = fmaf(av, w0.x, acc[r][0]);
                    acc[r][1] = fmaf(av, w0.y, acc[r][1]);
                    acc[r][2] = fmaf(av, w0.z, acc[r][2]);
                    acc[r][3] = fmaf(av, w0.w, acc[r][3]);
                    acc[r][4] = fmaf(av, w1.x, acc[r][4]);
                    acc[r][5] = fmaf(av, w1.y, acc[r][5]);
                    acc[r][6] = fmaf(av, w1.z, acc[r][6]);
                    acc[r][7] = fmaf(av, w1.w, acc[r][7]);
                }
            }
            __syncthreads();
        }

#pragma unroll
        for (int r = 0; r < 4; ++r) {
            size_t gi = (size_t)(row0 + ty * 4 + r) * F + tx * 8;
            float4 o0 = {acc[r][0], acc[r][1], acc[r][2], acc[r][3]};
            float4 o1 = {acc[r][4], acc[r][5], acc[r][6], acc[r][7]};
            *(float4*)(g_h + gi) = o0;
            *(float4*)(g_h + gi + 4) = o1;
        }
    } else {
        // ===================== SORT (batch b, 512 threads) =====================
        int b = blockIdx.x - 128;

        for (int j = t; j < N; j += 512) { u.s.key[j] = -g_e2[b * N + j]; u.s.sid[j] = j; }
        __syncthreads();

        for (int k2 = 2; k2 <= N; k2 <<= 1) {
            for (int j2 = k2 >> 1; j2 > 0; j2 >>= 1) {
                for (int tt = t; tt < N; tt += 512) {
                    int ixj = tt ^ j2;
                    if (ixj > tt) {
                        bool up = ((tt & k2) == 0);
                        float ka = u.s.key[tt], kb = u.s.key[ixj];
                        if ((ka > kb) == up) {
                            u.s.key[tt] = kb; u.s.key[ixj] = ka;
                            int tmp = u.s.sid[tt]; u.s.sid[tt] = u.s.sid[ixj]; u.s.sid[ixj] = tmp;
                        }
                    }
                }
                __syncthreads();
            }
        }

        // exp tables + per-thread (4 consecutive) local scalar prefix pieces
        float lpi[4], lni[4];
        float accp = 0.f, accn = 0.f;
#pragma unroll
        for (int i = 0; i < 4; ++i) {
            int j = t * 4 + i;
            float kv = u.s.key[j];
            float p2 = expf(-kv);
            float n2 = expf(-GALPHA * kv);
            g_perm[b * N + j] = u.s.sid[j];
            g_sp2[b * N + j] = p2;
            g_sn2[b * N + j] = n2;
            accp += p2; accn += n2;
            lpi[i] = accp; lni[i] = accn;
        }
        u.s.totP[t] = accp;
        u.s.totN[t] = accn;
        __syncthreads();

        // H-S inclusive scan over 512 thread totals
#pragma unroll
        for (int off = 1; off < 512; off <<= 1) {
            float vp = 0.f, vn = 0.f;
            if (t >= off) { vp = u.s.totP[t - off]; vn = u.s.totN[t - off]; }
            __syncthreads();
            u.s.totP[t] += vp; u.s.totN[t] += vn;
            __syncthreads();
        }
        float exP = u.s.totP[t] - accp;
        float exN = u.s.totN[t] - accn;
        size_t o = (size_t)b * (N + 1);
#pragma unroll
        for (int i = 0; i < 4; ++i) {
            int j = t * 4 + i;
            g_sP[o + j] = exP + (i == 0 ? 0.f : lpi[i - 1]);
            g_sN[o + j] = exN + (i == 0 ? 0.f : lni[i - 1]);
        }
        if (t == 511) { g_sP[o + N] = u.s.totP[511]; g_sN[o + N] = u.s.totN[511]; }

        // per-row threshold index
        for (int row = t; row < N; row += 512) {
            float e1 = g_e1[b * N + row];
            int lo = 0, hi = N;
            while (lo < hi) {
                int m = (lo + hi) >> 1;
                if (u.s.key[m] < e1) lo = m + 1; else hi = m;
            }
            g_kk[b * N + row] = lo;
        }
    }
}

// ---------------------------------------------------------------------------
// Kernel 3: per-chunk vector totals (perm preloaded -> batched h gathers)
// ---------------------------------------------------------------------------
__global__ __launch_bounds__(128) void k_ctot() {
    int c = blockIdx.x, b = blockIdx.y, f = threadIdx.x;
    int jb = b * N + c * CH;

    int rw[CH];
#pragma unroll
    for (int jj = 0; jj < CH; ++jj) rw[jj] = g_perm[jb + jj];

    float tp = 0.f, tn = 0.f;
#pragma unroll
    for (int jj = 0; jj < CH; ++jj) {
        float hv = g_h[((size_t)(b * N + rw[jj])) * F + f];
        tp = fmaf(g_sp2[jb + jj], hv, tp);
        tn = fmaf(g_sn2[jb + jj], hv, tn);
    }
    size_t ob = ((size_t)(b * NCH + c)) * F + f;
    g_ctP[ob] = tp;
    g_ctN[ob] = tn;
}

// ---------------------------------------------------------------------------
// Kernel 3b: super-group totals (8 chunks each)
// ---------------------------------------------------------------------------
__global__ __launch_bounds__(128) void k_stot() {
    int g = blockIdx.x, b = blockIdx.y, f = threadIdx.x;
    size_t base = ((size_t)(b * NCH + g * 8)) * F + f;
    float sp = 0.f, sn = 0.f;
#pragma unroll
    for (int c = 0; c < 8; ++c) {
        sp += g_ctP[base + (size_t)c * F];
        sn += g_ctN[base + (size_t)c * F];
    }
    size_t ob = ((size_t)(b * NSG + g)) * F + f;
    g_stP[ob] = sp;
    g_stN[ob] = sn;
}

// ---------------------------------------------------------------------------
// Kernel 4: per-chunk offset via 2-level totals + write full prefixes
// ---------------------------------------------------------------------------
__global__ __launch_bounds__(128) void k_scanlocal() {
    int c = blockIdx.x, b = blockIdx.y, f = threadIdx.x;
    int g = c >> 3, r = c & 7;

    float offP = 0.f, offN = 0.f;
    size_t stb = ((size_t)b * NSG) * F + f;
#pragma unroll
    for (int gg = 0; gg < NSG - 1; ++gg) {
        float vp = g_stP[stb + (size_t)gg * F];
        float vn = g_stN[stb + (size_t)gg * F];
        if (gg < g) { offP += vp; offN += vn; }
    }
    size_t ctb = ((size_t)(b * NCH + g * 8)) * F + f;
#pragma unroll
    for (int cc = 0; cc < 7; ++cc) {
        float vp = g_ctP[ctb + (size_t)cc * F];
        float vn = g_ctN[ctb + (size_t)cc * F];
        if (cc < r) { offP += vp; offN += vn; }
    }

    int jb = b * N + c * CH;
    int rw[CH];
#pragma unroll
    for (int jj = 0; jj < CH; ++jj) rw[jj] = g_perm[jb + jj];

    float accP = offP, accN = offN;
    size_t sb = ((size_t)(b * (N + 1) + c * CH)) * F + f;
#pragma unroll
    for (int jj = 0; jj < CH; ++jj) {
        float hv = g_h[((size_t)(b * N + rw[jj])) * F + f];
        g_SP[sb + (size_t)jj * F] = accP;
        g_SN[sb + (size_t)jj * F] = accN;
        accP = fmaf(g_sp2[jb + jj], hv, accP);
        accN = fmaf(g_sn2[jb + jj], hv, accN);
    }
    if (c == NCH - 1) {
        g_SP[((size_t)(b * (N + 1) + N)) * F + f] = accP;
        g_SN[((size_t)(b * (N + 1) + N)) * F + f] = accN;
    }
}

// ---------------------------------------------------------------------------
// Kernel 5: per-row O(1) lookup + elu epilogue
// ---------------------------------------------------------------------------
__global__ __launch_bounds__(128) void k_out(float* __restrict__ out) {
    __shared__ int   kk[32];
    __shared__ float p1s[32], n1s[32], sps[32], sns[32];

    int t = threadIdx.x;
    int b = blockIdx.y;
    int i0 = blockIdx.x * 32;

    if (t < 32) {
        int i = b * N + i0 + t;
        int k = g_kk[i];
        kk[t] = k;
        p1s[t] = g_P1[i];
        n1s[t] = g_N1[i];
        sps[t] = g_sP[(size_t)b * (N + 1) + k];
        sns[t] = g_sN[(size_t)b * (N + 1) + k];
    }
    __syncthreads();

    float totNf = g_SN[((size_t)(b * (N + 1) + N)) * F + t];
    float totNs = g_sN[(size_t)b * (N + 1) + N];

#pragma unroll 4
    for (int r = 0; r < 32; ++r) {
        int k = kk[r];
        size_t sb = ((size_t)(b * (N + 1) + k)) * F + t;
        float SPf = g_SP[sb];
        float SNf = g_SN[sb];

        float P1 = p1s[r], N1v = n1s[r];
        float den = fmaf(P1, sps[r], N1v * (totNs - sns[r]));
        float num = fmaf(P1, SPf, N1v * (totNf - SNf));
        float hv_i = g_h[((size_t)(b * N + i0 + r)) * F + t];
        float x = num / den + GALPHA * hv_i;
        out[((size_t)(b * N + i0 + r)) * F + t] = (x > 0.f) ? x : expm1f(x);
    }
}

extern "C" void kernel_launch(void* const* d_in, const int* in_sizes, int n_in,
                              void* d_out, int out_size) {
    const float* text = (const float*)d_in[0];
    // d_in[1] = adj : unused by the reference computation
    const float* W = (const float*)d_in[2];
    const float* a = (const float*)d_in[3];
    float* out = (float*)d_out;

    k_e<<<(B * N) / 256, 256>>>(text, W, a);
    k_gemsort<<<128 + B, 512>>>(text, W);
    dim3 gc(NCH, B);
    k_ctot<<<gc, 128>>>();
    dim3 gs(NSG, B);
    k_stot<<<gs, 128>>>();
    k_scanlocal<<<gc, 128>>>();
    dim3 go(N / 32, B);
    k_out<<<go, 128>>>(out);
}

// round 13
// speedup vs baseline: 1.5499x; 1.2122x over previous
#include <cuda_runtime.h>
#include <math.h>

#define B 8
#define N 2048
#define C 128
#define F 128
#define GALPHA 0.2f
#define NCH 64
#define CH 32    /* N / NCH */
#define NSG 8    /* super-groups of 8 chunks */

__device__ float g_h[B*N*F];
__device__ float g_e1[B*N], g_e2[B*N];
__device__ float g_P1[B*N], g_N1[B*N];
__device__ int   g_perm[B*N];
__device__ float g_sp2[B*N], g_sn2[B*N];   // sorted exp(e2), exp(0.2*e2)
__device__ float g_ctP[B*NCH*F];           // vector chunk totals
__device__ float g_ctN[B*NCH*F];
__device__ float g_stP[B*NSG*F];           // super-group totals
__device__ float g_stN[B*NSG*F];
__device__ float g_SP[B*(N+1)*F];          // full exclusive prefix of P2*h (sorted)
__device__ float g_SN[B*(N+1)*F];
__device__ float g_sP[B*(N+1)];            // scalar exclusive prefixes
__device__ float g_sN[B*(N+1)];
__device__ int   g_kk[B*N];                // per-row threshold index

// ---------------------------------------------------------------------------
// Kernel 1: h = text @ W.  128 blocks x 256 thr (32tx x 8ty), thread tile
// 16 rows x 4 cols. W loads conflict-free LDS.128; a loads are broadcasts.
// Fused e1/e2 + exp tables epilogue (warp owns 16 whole rows).
// ---------------------------------------------------------------------------
__global__ __launch_bounds__(256) void k_gemm_h(const float* __restrict__ text,
                                                const float* __restrict__ W,
                                                const float* __restrict__ a) {
    __shared__ float a_sh[128][33];     // text panel: 128 rows x 32 k
    __shared__ float W_sh[32][128];     // W panel: 32 k x 128 cols
    __shared__ float avec[2 * F];

    int t = threadIdx.x;
    int row0 = blockIdx.x * 128;
    if (t < 64) ((float4*)avec)[t] = ((const float4*)a)[t];

    int tx = t & 31;        // column group: cols tx*4 .. tx*4+3
    int ty = t >> 5;        // warp id: rows ty*16 .. ty*16+15

    float acc[16][4];
#pragma unroll
    for (int r = 0; r < 16; ++r)
#pragma unroll
        for (int c = 0; c < 4; ++c) acc[r][c] = 0.f;

    for (int k0 = 0; k0 < C; k0 += 32) {
        // stage text panel 128x32 (4 float4 per thread, coalesced)
#pragma unroll
        for (int i = 0; i < 4; ++i) {
            int idx = t + i * 256;
            int r = idx >> 3, c4 = idx & 7;
            float4 v = *(const float4*)(text + (size_t)(row0 + r) * C + k0 + c4 * 4);
            a_sh[r][c4 * 4 + 0] = v.x;
            a_sh[r][c4 * 4 + 1] = v.y;
            a_sh[r][c4 * 4 + 2] = v.z;
            a_sh[r][c4 * 4 + 3] = v.w;
        }
        // stage W panel 32x128
#pragma unroll
        for (int i = 0; i < 4; ++i) {
            int idx = t + i * 256;
            int kr = idx >> 5, f4 = idx & 31;
            *(float4*)&W_sh[kr][f4 * 4] =
                *(const float4*)(W + (size_t)(k0 + kr) * F + f4 * 4);
        }
        __syncthreads();

#pragma unroll 8
        for (int k = 0; k < 32; ++k) {
            float4 w4 = *(const float4*)&W_sh[k][tx * 4];
#pragma unroll
            for (int r = 0; r < 16; ++r) {
                float av = a_sh[ty * 16 + r][k];
                acc[r][0] = fmaf(av, w4.x, acc[r][0]);
                acc[r][1] = fmaf(av, w4.y, acc[r][1]);
                acc[r][2] = fmaf(av, w4.z, acc[r][2]);
                acc[r][3] = fmaf(av, w4.w, acc[r][3]);
            }
        }
        __syncthreads();
    }

    // epilogue: store h + per-row e1/e2 (full-warp reduction; warp owns rows)
#pragma unroll
    for (int r = 0; r < 16; ++r) {
        int row = row0 + ty * 16 + r;
        size_t gi = (size_t)row * F + tx * 4;
        float4 o = {acc[r][0], acc[r][1], acc[r][2], acc[r][3]};
        *(float4*)(g_h + gi) = o;

        float p1 = 0.f, p2 = 0.f;
#pragma unroll
        for (int c = 0; c < 4; ++c) {
            p1 = fmaf(acc[r][c], avec[tx * 4 + c], p1);
            p2 = fmaf(acc[r][c], avec[F + tx * 4 + c], p2);
        }
#pragma unroll
        for (int o2 = 16; o2 > 0; o2 >>= 1) {
            p1 += __shfl_xor_sync(0xffffffffu, p1, o2);
            p2 += __shfl_xor_sync(0xffffffffu, p2, o2);
        }
        if (tx == 0) {
            g_e1[row] = p1;
            g_e2[row] = p2;
            g_P1[row] = expf(p1);
            g_N1[row] = expf(GALPHA * p1);
        }
    }
}

// ---------------------------------------------------------------------------
// Kernel 2: per-batch bitonic sort of (-e2) ascending with index payload.
// Epilogue: sorted exp tables, scalar exclusive prefix scans, threshold idx.
// ---------------------------------------------------------------------------
__global__ __launch_bounds__(1024) void k_sort() {
    __shared__ float key[N];
    __shared__ int   sid[N];
    __shared__ float s1[N], s2[N];
    int b = blockIdx.x, t = threadIdx.x;

    for (int j = t; j < N; j += 1024) { key[j] = -g_e2[b * N + j]; sid[j] = j; }
    __syncthreads();

    for (int k2 = 2; k2 <= N; k2 <<= 1) {
        for (int j2 = k2 >> 1; j2 > 0; j2 >>= 1) {
            for (int tt = t; tt < N; tt += 1024) {
                int ixj = tt ^ j2;
                if (ixj > tt) {
                    bool up = ((tt & k2) == 0);
                    float ka = key[tt], kb = key[ixj];
                    if ((ka > kb) == up) {
                        key[tt] = kb; key[ixj] = ka;
                        int tmp = sid[tt]; sid[tt] = sid[ixj]; sid[ixj] = tmp;
                    }
                }
            }
            __syncthreads();
        }
    }

    int j0 = t, j1 = t + 1024;
    float p20 = expf(-key[j0]), p21 = expf(-key[j1]);
    float n20 = expf(-GALPHA * key[j0]), n21 = expf(-GALPHA * key[j1]);
    g_perm[b * N + j0] = sid[j0];  g_perm[b * N + j1] = sid[j1];
    g_sp2[b * N + j0] = p20;       g_sp2[b * N + j1] = p21;
    g_sn2[b * N + j0] = n20;       g_sn2[b * N + j1] = n21;
    s1[j0] = p20; s1[j1] = p21;
    s2[j0] = n20; s2[j1] = n21;
    __syncthreads();

#pragma unroll
    for (int off = 1; off < N; off <<= 1) {
        float a0 = 0.f, a1 = 0.f, c0 = 0.f, c1 = 0.f;
        if (j0 >= off) { a0 = s1[j0 - off]; c0 = s2[j0 - off]; }
        if (j1 >= off) { a1 = s1[j1 - off]; c1 = s2[j1 - off]; }
        __syncthreads();
        s1[j0] += a0; s2[j0] += c0;
        s1[j1] += a1; s2[j1] += c1;
        __syncthreads();
    }
    size_t o = (size_t)b * (N + 1);
    g_sP[o + j0] = s1[j0] - p20;  g_sP[o + j1] = s1[j1] - p21;
    g_sN[o + j0] = s2[j0] - n20;  g_sN[o + j1] = s2[j1] - n21;
    if (t == 1023) { g_sP[o + N] = s1[N - 1]; g_sN[o + N] = s2[N - 1]; }

    for (int row = t; row < N; row += 1024) {
        float e1 = g_e1[b * N + row];
        int lo = 0, hi = N;
        while (lo < hi) {
            int m = (lo + hi) >> 1;
            if (key[m] < e1) lo = m + 1; else hi = m;
        }
        g_kk[b * N + row] = lo;
    }
}

// ---------------------------------------------------------------------------
// Kernel 3: per-chunk vector totals (perm preloaded -> batched h gathers)
// ---------------------------------------------------------------------------
__global__ __launch_bounds__(128) void k_ctot() {
    int c = blockIdx.x, b = blockIdx.y, f = threadIdx.x;
    int jb = b * N + c * CH;

    int rw[CH];
#pragma unroll
    for (int jj = 0; jj < CH; ++jj) rw[jj] = g_perm[jb + jj];

    float tp = 0.f, tn = 0.f;
#pragma unroll
    for (int jj = 0; jj < CH; ++jj) {
        float hv = g_h[((size_t)(b * N + rw[jj])) * F + f];
        tp = fmaf(g_sp2[jb + jj], hv, tp);
        tn = fmaf(g_sn2[jb + jj], hv, tn);
    }
    size_t ob = ((size_t)(b * NCH + c)) * F + f;
    g_ctP[ob] = tp;
    g_ctN[ob] = tn;
}

// ---------------------------------------------------------------------------
// Kernel 3b: super-group totals (8 chunks each)
// ---------------------------------------------------------------------------
__global__ __launch_bounds__(128) void k_stot() {
    int g = blockIdx.x, b = blockIdx.y, f = threadIdx.x;
    size_t base = ((size_t)(b * NCH + g * 8)) * F + f;
    float sp = 0.f, sn = 0.f;
#pragma unroll
    for (int c = 0; c < 8; ++c) {
        sp += g_ctP[base + (size_t)c * F];
        sn += g_ctN[base + (size_t)c * F];
    }
    size_t ob = ((size_t)(b * NSG + g)) * F + f;
    g_stP[ob] = sp;
    g_stN[ob] = sn;
}

// ---------------------------------------------------------------------------
// Kernel 4: per-chunk offset via 2-level totals + write full prefixes
// ---------------------------------------------------------------------------
__global__ __launch_bounds__(128) void k_scanlocal() {
    int c = blockIdx.x, b = blockIdx.y, f = threadIdx.x;
    int g = c >> 3, r = c & 7;

    float offP = 0.f, offN = 0.f;
    size_t stb = ((size_t)b * NSG) * F + f;
#pragma unroll
    for (int gg = 0; gg < NSG - 1; ++gg) {
        float vp = g_stP[stb + (size_t)gg * F];
        float vn = g_stN[stb + (size_t)gg * F];
        if (gg < g) { offP += vp; offN += vn; }
    }
    size_t ctb = ((size_t)(b * NCH + g * 8)) * F + f;
#pragma unroll
    for (int cc = 0; cc < 7; ++cc) {
        float vp = g_ctP[ctb + (size_t)cc * F];
        float vn = g_ctN[ctb + (size_t)cc * F];
        if (cc < r) { offP += vp; offN += vn; }
    }

    int jb = b * N + c * CH;
    int rw[CH];
#pragma unroll
    for (int jj = 0; jj < CH; ++jj) rw[jj] = g_perm[jb + jj];

    float accP = offP, accN = offN;
    size_t sb = ((size_t)(b * (N + 1) + c * CH)) * F + f;
#pragma unroll
    for (int jj = 0; jj < CH; ++jj) {
        float hv = g_h[((size_t)(b * N + rw[jj])) * F + f];
        g_SP[sb + (size_t)jj * F] = accP;
        g_SN[sb + (size_t)jj * F] = accN;
        accP = fmaf(g_sp2[jb + jj], hv, accP);
        accN = fmaf(g_sn2[jb + jj], hv, accN);
    }
    if (c == NCH - 1) {
        g_SP[((size_t)(b * (N + 1) + N)) * F + f] = accP;
        g_SN[((size_t)(b * (N + 1) + N)) * F + f] = accN;
    }
}

// ---------------------------------------------------------------------------
// Kernel 5: per-row O(1) lookup + elu epilogue
// ---------------------------------------------------------------------------
__global__ __launch_bounds__(128) void k_out(float* __restrict__ out) {
    __shared__ int   kk[32];
    __shared__ float p1s[32], n1s[32], sps[32], sns[32];

    int t = threadIdx.x;
    int b = blockIdx.y;
    int i0 = blockIdx.x * 32;

    if (t < 32) {
        int i = b * N + i0 + t;
        int k = g_kk[i];
        kk[t] = k;
        p1s[t] = g_P1[i];
        n1s[t] = g_N1[i];
        sps[t] = g_sP[(size_t)b * (N + 1) + k];
        sns[t] = g_sN[(size_t)b * (N + 1) + k];
    }
    __syncthreads();

    float totNf = g_SN[((size_t)(b * (N + 1) + N)) * F + t];
    float totNs = g_sN[(size_t)b * (N + 1) + N];

#pragma unroll 4
    for (int r = 0; r < 32; ++r) {
        int k = kk[r];
        size_t sb = ((size_t)(b * (N + 1) + k)) * F + t;
        float SPf = g_SP[sb];
        float SNf = g_SN[sb];

        float P1 = p1s[r], N1v = n1s[r];
        float den = fmaf(P1, sps[r], N1v * (totNs - sns[r]));
        float num = fmaf(P1, SPf, N1v * (totNf - SNf));
        float hv_i = g_h[((size_t)(b * N + i0 + r)) * F + t];
        float x = num / den + GALPHA * hv_i;
        out[((size_t)(b * N + i0 + r)) * F + t] = (x > 0.f) ? x : expm1f(x);
    }
}

extern "C" void kernel_launch(void* const* d_in, const int* in_sizes, int n_in,
                              void* d_out, int out_size) {
    const float* text = (const float*)d_in[0];
    // d_in[1] = adj : unused by the reference computation
    const float* W = (const float*)d_in[2];
    const float* a = (const float*)d_in[3];
    float* out = (float*)d_out;

    k_gemm_h<<<(B * N) / 128, 256>>>(text, W, a);
    k_sort<<<B, 1024>>>();
    dim3 gc(NCH, B);
    k_ctot<<<gc, 128>>>();
    dim3 gs(NSG, B);
    k_stot<<<gs, 128>>>();
    k_scanlocal<<<gc, 128>>>();
    dim3 go(N / 32, B);
    k_out<<<go, 128>>>(out);
}